// round 7
// baseline (speedup 1.0000x reference)
#include <cuda_runtime.h>
#include <cstdint>

#define OUT_SEGS 100000
#define FDIM 128

// Scratch (allocation-free rule): pooled sums [OUT_SEGS, 128] + counts [OUT_SEGS]
__device__ float g_pooled[(size_t)OUT_SEGS * FDIM];
__device__ float g_count[OUT_SEGS];

// ---------------------------------------------------------------------------
// 1) zero scratch (plain stores; 51.2MB fits in L2 and stays warm for scatter)
__global__ void zero_kernel() {
    size_t total = (size_t)OUT_SEGS * FDIM;
    size_t stride = (size_t)gridDim.x * blockDim.x;
    for (size_t i = (size_t)blockIdx.x * blockDim.x + threadIdx.x; i < total; i += stride)
        g_pooled[i] = 0.0f;
    for (size_t i = (size_t)blockIdx.x * blockDim.x + threadIdx.x; i < OUT_SEGS; i += stride)
        g_count[i] = 0.0f;
}

// ---------------------------------------------------------------------------
// 2) scatter: one full warp per 2 input rows, dense v4 layout per row.
//    Both streaming loads issue before either REDG -> 2 independent DRAM
//    reads in flight per warp (MLP=2 on the latency path). REDG is
//    fire-and-forget. Each red.global.add.v4 covers a dense 512B span.
__global__ void scatter_kernel(const float* __restrict__ x,
                               const int* __restrict__ index, int N) {
    int warp_global = (blockIdx.x * blockDim.x + threadIdx.x) >> 5;
    int lane = threadIdx.x & 31;

    int row0 = warp_global * 2;
    if (row0 >= N) return;
    int row1 = row0 + 1;
    bool d1 = (row1 < N);

    int seg0 = index[row0];
    int seg1 = d1 ? index[row1] : seg0;

    const float* src0 = x + (size_t)row0 * FDIM + lane * 4;
    const float* src1 = x + (size_t)row1 * FDIM + lane * 4;

    float4 v0, v1;
    asm volatile("ld.global.cs.v4.f32 {%0, %1, %2, %3}, [%4];"
                 : "=f"(v0.x), "=f"(v0.y), "=f"(v0.z), "=f"(v0.w)
                 : "l"(src0));
    if (d1)
        asm volatile("ld.global.cs.v4.f32 {%0, %1, %2, %3}, [%4];"
                     : "=f"(v1.x), "=f"(v1.y), "=f"(v1.z), "=f"(v1.w)
                     : "l"(src1));

    float* dst0 = g_pooled + (size_t)seg0 * FDIM + lane * 4;
    asm volatile("red.global.add.v4.f32 [%0], {%1, %2, %3, %4};"
                 :: "l"(dst0), "f"(v0.x), "f"(v0.y), "f"(v0.z), "f"(v0.w)
                 : "memory");
    if (d1) {
        float* dst1 = g_pooled + (size_t)seg1 * FDIM + lane * 4;
        asm volatile("red.global.add.v4.f32 [%0], {%1, %2, %3, %4};"
                     :: "l"(dst1), "f"(v1.x), "f"(v1.y), "f"(v1.z), "f"(v1.w)
                     : "memory");
    }

    if (lane == 0) {
        atomicAdd(g_count + seg0, 1.0f);
        if (d1) atomicAdd(g_count + seg1, 1.0f);
    }
}

// ---------------------------------------------------------------------------
// 3) gather (fused finalize): one warp per 4 output rows, float4 per lane.
//    pooled reads: ld.global.nc.L2::cache_hint (evict-last policy)
//    out writes:   st.global.cs (evict-first)
__global__ void gather_kernel(const int* __restrict__ index,
                              float* __restrict__ out, int N) {
    int warp_global = (blockIdx.x * blockDim.x + threadIdx.x) >> 5;
    int lane = threadIdx.x & 31;

    int row0 = warp_global * 4;
    if (row0 >= N) return;
    int row1 = row0 + 1, row2 = row0 + 2, row3 = row0 + 3;
    bool d1 = row1 < N, d2 = row2 < N, d3 = row3 < N;

    uint64_t policy;
    asm volatile("createpolicy.fractional.L2::evict_last.b64 %0, 1.0;"
                 : "=l"(policy));

    int seg0 = index[row0];
    int seg1 = d1 ? index[row1] : seg0;
    int seg2 = d2 ? index[row2] : seg0;
    int seg3 = d3 ? index[row3] : seg0;

    const float* p0 = g_pooled + (size_t)seg0 * FDIM + lane * 4;
    const float* p1 = g_pooled + (size_t)seg1 * FDIM + lane * 4;
    const float* p2 = g_pooled + (size_t)seg2 * FDIM + lane * 4;
    const float* p3 = g_pooled + (size_t)seg3 * FDIM + lane * 4;

    float4 a, b, c, d;
    asm volatile("ld.global.nc.L2::cache_hint.v4.f32 {%0, %1, %2, %3}, [%4], %5;"
                 : "=f"(a.x), "=f"(a.y), "=f"(a.z), "=f"(a.w)
                 : "l"(p0), "l"(policy));
    asm volatile("ld.global.nc.L2::cache_hint.v4.f32 {%0, %1, %2, %3}, [%4], %5;"
                 : "=f"(b.x), "=f"(b.y), "=f"(b.z), "=f"(b.w)
                 : "l"(p1), "l"(policy));
    asm volatile("ld.global.nc.L2::cache_hint.v4.f32 {%0, %1, %2, %3}, [%4], %5;"
                 : "=f"(c.x), "=f"(c.y), "=f"(c.z), "=f"(c.w)
                 : "l"(p2), "l"(policy));
    asm volatile("ld.global.nc.L2::cache_hint.v4.f32 {%0, %1, %2, %3}, [%4], %5;"
                 : "=f"(d.x), "=f"(d.y), "=f"(d.z), "=f"(d.w)
                 : "l"(p3), "l"(policy));

    float inv0 = 1.0f / (__ldg(g_count + seg0) + 1e-9f);
    float inv1 = 1.0f / (__ldg(g_count + seg1) + 1e-9f);
    float inv2 = 1.0f / (__ldg(g_count + seg2) + 1e-9f);
    float inv3 = 1.0f / (__ldg(g_count + seg3) + 1e-9f);

    a.x *= inv0; a.y *= inv0; a.z *= inv0; a.w *= inv0;
    b.x *= inv1; b.y *= inv1; b.z *= inv1; b.w *= inv1;
    c.x *= inv2; c.y *= inv2; c.z *= inv2; c.w *= inv2;
    d.x *= inv3; d.y *= inv3; d.z *= inv3; d.w *= inv3;

    float* o0 = out + (size_t)row0 * FDIM + lane * 4;
    asm volatile("st.global.cs.v4.f32 [%0], {%1, %2, %3, %4};"
                 :: "l"(o0), "f"(a.x), "f"(a.y), "f"(a.z), "f"(a.w) : "memory");
    if (d1) {
        float* o1 = out + (size_t)row1 * FDIM + lane * 4;
        asm volatile("st.global.cs.v4.f32 [%0], {%1, %2, %3, %4};"
                     :: "l"(o1), "f"(b.x), "f"(b.y), "f"(b.z), "f"(b.w) : "memory");
    }
    if (d2) {
        float* o2 = out + (size_t)row2 * FDIM + lane * 4;
        asm volatile("st.global.cs.v4.f32 [%0], {%1, %2, %3, %4};"
                     :: "l"(o2), "f"(c.x), "f"(c.y), "f"(c.z), "f"(c.w) : "memory");
    }
    if (d3) {
        float* o3 = out + (size_t)row3 * FDIM + lane * 4;
        asm volatile("st.global.cs.v4.f32 [%0], {%1, %2, %3, %4};"
                     :: "l"(o3), "f"(d.x), "f"(d.y), "f"(d.z), "f"(d.w) : "memory");
    }
}

// ---------------------------------------------------------------------------
extern "C" void kernel_launch(void* const* d_in, const int* in_sizes, int n_in,
                              void* d_out, int out_size) {
    const float* x   = (const float*)d_in[0];
    const int* index = (const int*)d_in[1];
    float* out = (float*)d_out;

    int N = in_sizes[1];  // number of rows (index has N elements)

    // 1) zero scratch
    zero_kernel<<<1184, 256>>>();

    // 2) scatter: warp per 2 rows
    {
        int threads = 256;
        int rows_per_block = (threads / 32) * 2;
        int blocks = (N + rows_per_block - 1) / rows_per_block;
        scatter_kernel<<<blocks, threads>>>(x, index, N);
    }

    // 3) gather (fused finalize): warp per 4 rows
    {
        int threads = 256;
        int rows_per_block = (threads / 32) * 4;
        int blocks = (N + rows_per_block - 1) / rows_per_block;
        gather_kernel<<<blocks, threads>>>(index, out, N);
    }
}

// round 9
// speedup vs baseline: 1.3333x; 1.3333x over previous
#include <cuda_runtime.h>
#include <cstdint>

#define OUT_SEGS 100000
#define FDIM 128
#define NMAX 1000000
#define CHUNK 512
#define NCHUNKS ((OUT_SEGS + CHUNK - 1) / CHUNK)   // 196

// Scratch (allocation-free rule)
__device__ float g_mean[(size_t)OUT_SEGS * FDIM];  // per-segment mean [100K,128]
__device__ int   g_cnt[OUT_SEGS];
__device__ int   g_off[OUT_SEGS];
__device__ int   g_cur[OUT_SEGS];
__device__ int   g_part[NCHUNKS];
__device__ int   g_perm[NMAX];

// ---------------------------------------------------------------------------
// Z: zero histogram
__global__ void zero_cnt_kernel() {
    int stride = gridDim.x * blockDim.x;
    for (int i = blockIdx.x * blockDim.x + threadIdx.x; i < OUT_SEGS; i += stride)
        g_cnt[i] = 0;
}

// H: histogram of index
__global__ void hist_kernel(const int* __restrict__ index, int N) {
    int stride = gridDim.x * blockDim.x;
    for (int i = blockIdx.x * blockDim.x + threadIdx.x; i < N; i += stride)
        atomicAdd(&g_cnt[index[i]], 1);
}

// S1: per-chunk sums
__global__ void scan1_kernel() {
    __shared__ int sm[CHUNK];
    int b = blockIdx.x;
    int t = threadIdx.x;
    int i = b * CHUNK + t;
    sm[t] = (i < OUT_SEGS) ? g_cnt[i] : 0;
    __syncthreads();
    for (int s = CHUNK / 2; s > 0; s >>= 1) {
        if (t < s) sm[t] += sm[t + s];
        __syncthreads();
    }
    if (t == 0) g_part[b] = sm[0];
}

// S2: exclusive scan of chunk sums (single block, 256 threads >= NCHUNKS)
__global__ void scan2_kernel() {
    __shared__ int sm[256];
    int t = threadIdx.x;
    int v = (t < NCHUNKS) ? g_part[t] : 0;
    sm[t] = v;
    __syncthreads();
    // Hillis-Steele inclusive
    for (int d = 1; d < 256; d <<= 1) {
        int add = (t >= d) ? sm[t - d] : 0;
        __syncthreads();
        sm[t] += add;
        __syncthreads();
    }
    if (t < NCHUNKS) g_part[t] = sm[t] - v;  // exclusive
}

// S3: per-chunk exclusive scan + chunk base -> offsets, cursor
__global__ void scan3_kernel() {
    __shared__ int sm[CHUNK];
    int b = blockIdx.x;
    int t = threadIdx.x;
    int i = b * CHUNK + t;
    int v = (i < OUT_SEGS) ? g_cnt[i] : 0;
    sm[t] = v;
    __syncthreads();
    for (int d = 1; d < CHUNK; d <<= 1) {
        int add = (t >= d) ? sm[t - d] : 0;
        __syncthreads();
        sm[t] += add;
        __syncthreads();
    }
    if (i < OUT_SEGS) {
        int excl = sm[t] - v + g_part[b];
        g_off[i] = excl;
        g_cur[i] = excl;
    }
}

// P: build permutation (row ids grouped by segment)
__global__ void perm_kernel(const int* __restrict__ index, int N) {
    int stride = gridDim.x * blockDim.x;
    for (int i = blockIdx.x * blockDim.x + threadIdx.x; i < N; i += stride) {
        int seg = index[i];
        int pos = atomicAdd(&g_cur[seg], 1);
        g_perm[pos] = i;
    }
}

// R: warp per segment -> sum rows in registers, store mean once (evict-last).
//    Atomic-free on the f32 data. Loop unrolled x2 for MLP.
__global__ void reduce_kernel(const float* __restrict__ x) {
    int warp_global = (blockIdx.x * blockDim.x + threadIdx.x) >> 5;
    int lane = threadIdx.x & 31;
    if (warp_global >= OUT_SEGS) return;
    int s = warp_global;

    int start = g_off[s];
    int cnt = g_cnt[s];
    int end = start + cnt;

    float4 acc = make_float4(0.f, 0.f, 0.f, 0.f);

    int j = start;
    for (; j + 1 < end; j += 2) {
        int r0 = g_perm[j];
        int r1 = g_perm[j + 1];
        const float* s0 = x + (size_t)r0 * FDIM + lane * 4;
        const float* s1 = x + (size_t)r1 * FDIM + lane * 4;
        float4 v0, v1;
        asm volatile("ld.global.cs.v4.f32 {%0, %1, %2, %3}, [%4];"
                     : "=f"(v0.x), "=f"(v0.y), "=f"(v0.z), "=f"(v0.w) : "l"(s0));
        asm volatile("ld.global.cs.v4.f32 {%0, %1, %2, %3}, [%4];"
                     : "=f"(v1.x), "=f"(v1.y), "=f"(v1.z), "=f"(v1.w) : "l"(s1));
        acc.x += v0.x + v1.x; acc.y += v0.y + v1.y;
        acc.z += v0.z + v1.z; acc.w += v0.w + v1.w;
    }
    if (j < end) {
        int r0 = g_perm[j];
        const float* s0 = x + (size_t)r0 * FDIM + lane * 4;
        float4 v0;
        asm volatile("ld.global.cs.v4.f32 {%0, %1, %2, %3}, [%4];"
                     : "=f"(v0.x), "=f"(v0.y), "=f"(v0.z), "=f"(v0.w) : "l"(s0));
        acc.x += v0.x; acc.y += v0.y; acc.z += v0.z; acc.w += v0.w;
    }

    float inv = 1.0f / ((float)cnt + 1e-9f);
    acc.x *= inv; acc.y *= inv; acc.z *= inv; acc.w *= inv;

    uint64_t policy;
    asm volatile("createpolicy.fractional.L2::evict_last.b64 %0, 1.0;"
                 : "=l"(policy));
    float* dst = g_mean + (size_t)s * FDIM + lane * 4;
    asm volatile("st.global.L2::cache_hint.v4.f32 [%0], {%1, %2, %3, %4}, %5;"
                 :: "l"(dst), "f"(acc.x), "f"(acc.y), "f"(acc.z), "f"(acc.w),
                    "l"(policy) : "memory");
}

// G: gather = copy mean[index[row]] -> out[row]. Warp per 2 rows.
__global__ void gather_kernel(const int* __restrict__ index,
                              float* __restrict__ out, int N) {
    int warp_global = (blockIdx.x * blockDim.x + threadIdx.x) >> 5;
    int lane = threadIdx.x & 31;

    int row0 = warp_global * 2;
    int row1 = row0 + 1;
    if (row0 >= N) return;
    bool d1 = (row1 < N);

    uint64_t policy;
    asm volatile("createpolicy.fractional.L2::evict_last.b64 %0, 1.0;"
                 : "=l"(policy));

    int seg0 = index[row0];
    int seg1 = d1 ? index[row1] : seg0;

    const float* p0 = g_mean + (size_t)seg0 * FDIM + lane * 4;
    const float* p1 = g_mean + (size_t)seg1 * FDIM + lane * 4;

    float4 a, b;
    asm volatile("ld.global.nc.L2::cache_hint.v4.f32 {%0, %1, %2, %3}, [%4], %5;"
                 : "=f"(a.x), "=f"(a.y), "=f"(a.z), "=f"(a.w)
                 : "l"(p0), "l"(policy));
    asm volatile("ld.global.nc.L2::cache_hint.v4.f32 {%0, %1, %2, %3}, [%4], %5;"
                 : "=f"(b.x), "=f"(b.y), "=f"(b.z), "=f"(b.w)
                 : "l"(p1), "l"(policy));

    float* o0 = out + (size_t)row0 * FDIM + lane * 4;
    asm volatile("st.global.cs.v4.f32 [%0], {%1, %2, %3, %4};"
                 :: "l"(o0), "f"(a.x), "f"(a.y), "f"(a.z), "f"(a.w) : "memory");
    if (d1) {
        float* o1 = out + (size_t)row1 * FDIM + lane * 4;
        asm volatile("st.global.cs.v4.f32 [%0], {%1, %2, %3, %4};"
                     :: "l"(o1), "f"(b.x), "f"(b.y), "f"(b.z), "f"(b.w) : "memory");
    }
}

// ---------------------------------------------------------------------------
extern "C" void kernel_launch(void* const* d_in, const int* in_sizes, int n_in,
                              void* d_out, int out_size) {
    const float* x   = (const float*)d_in[0];
    const int* index = (const int*)d_in[1];
    float* out = (float*)d_out;

    int N = in_sizes[1];

    zero_cnt_kernel<<<98, 256>>>();
    hist_kernel<<<1184, 256>>>(index, N);
    scan1_kernel<<<NCHUNKS, CHUNK>>>();
    scan2_kernel<<<1, 256>>>();
    scan3_kernel<<<NCHUNKS, CHUNK>>>();
    perm_kernel<<<1184, 256>>>(index, N);

    // reduce: warp per segment
    {
        int threads = 256;
        int segs_per_block = threads / 32;
        int blocks = (OUT_SEGS + segs_per_block - 1) / segs_per_block;
        reduce_kernel<<<blocks, threads>>>(x);
    }

    // gather: warp per 2 rows
    {
        int threads = 256;
        int rows_per_block = (threads / 32) * 2;
        int blocks = (N + rows_per_block - 1) / rows_per_block;
        gather_kernel<<<blocks, threads>>>(index, out, N);
    }
}

// round 10
// speedup vs baseline: 1.4945x; 1.1208x over previous
#include <cuda_runtime.h>
#include <cstdint>

#define OUT_SEGS 100000
#define FDIM 128
#define NMAX 1000000
#define CHUNK 512
#define NCHUNKS ((OUT_SEGS + CHUNK - 1) / CHUNK)   // 196

// Scratch (allocation-free rule)
__device__ int g_cnt[OUT_SEGS];
__device__ int g_off[OUT_SEGS];
__device__ int g_cur[OUT_SEGS];
__device__ int g_part[NCHUNKS];
__device__ int g_perm[NMAX];

// ---------------------------------------------------------------------------
// Z: zero histogram
__global__ void zero_cnt_kernel() {
    int stride = gridDim.x * blockDim.x;
    for (int i = blockIdx.x * blockDim.x + threadIdx.x; i < OUT_SEGS; i += stride)
        g_cnt[i] = 0;
}

// H: histogram of index
__global__ void hist_kernel(const int* __restrict__ index, int N) {
    int stride = gridDim.x * blockDim.x;
    for (int i = blockIdx.x * blockDim.x + threadIdx.x; i < N; i += stride)
        atomicAdd(&g_cnt[index[i]], 1);
}

// S1: per-chunk sums
__global__ void scan1_kernel() {
    __shared__ int sm[CHUNK];
    int b = blockIdx.x;
    int t = threadIdx.x;
    int i = b * CHUNK + t;
    sm[t] = (i < OUT_SEGS) ? g_cnt[i] : 0;
    __syncthreads();
    for (int s = CHUNK / 2; s > 0; s >>= 1) {
        if (t < s) sm[t] += sm[t + s];
        __syncthreads();
    }
    if (t == 0) g_part[b] = sm[0];
}

// S2: exclusive scan of chunk sums (single block, 256 threads >= NCHUNKS)
__global__ void scan2_kernel() {
    __shared__ int sm[256];
    int t = threadIdx.x;
    int v = (t < NCHUNKS) ? g_part[t] : 0;
    sm[t] = v;
    __syncthreads();
    for (int d = 1; d < 256; d <<= 1) {
        int add = (t >= d) ? sm[t - d] : 0;
        __syncthreads();
        sm[t] += add;
        __syncthreads();
    }
    if (t < NCHUNKS) g_part[t] = sm[t] - v;  // exclusive
}

// S3: per-chunk exclusive scan + chunk base -> offsets, cursor
__global__ void scan3_kernel() {
    __shared__ int sm[CHUNK];
    int b = blockIdx.x;
    int t = threadIdx.x;
    int i = b * CHUNK + t;
    int v = (i < OUT_SEGS) ? g_cnt[i] : 0;
    sm[t] = v;
    __syncthreads();
    for (int d = 1; d < CHUNK; d <<= 1) {
        int add = (t >= d) ? sm[t - d] : 0;
        __syncthreads();
        sm[t] += add;
        __syncthreads();
    }
    if (i < OUT_SEGS) {
        int excl = sm[t] - v + g_part[b];
        g_off[i] = excl;
        g_cur[i] = excl;
    }
}

// P: build permutation (row ids grouped by segment)
__global__ void perm_kernel(const int* __restrict__ index, int N) {
    int stride = gridDim.x * blockDim.x;
    for (int i = blockIdx.x * blockDim.x + threadIdx.x; i < N; i += stride) {
        int seg = index[i];
        int pos = atomicAdd(&g_cur[seg], 1);
        g_perm[pos] = i;
    }
}

// RG: fused reduce + gather. Warp per segment:
//     pass 1: stream-read the segment's rows of x, accumulate in registers;
//     pass 2: write the mean directly to every output row of the segment.
//     No mean buffer, no atomics, no separate gather. Traffic = algorithmic
//     floor (read x once, write out once).
__global__ void reduce_write_kernel(const float* __restrict__ x,
                                    float* __restrict__ out) {
    int warp_global = (blockIdx.x * blockDim.x + threadIdx.x) >> 5;
    int lane = threadIdx.x & 31;
    if (warp_global >= OUT_SEGS) return;
    int s = warp_global;

    int start = g_off[s];
    int cnt = g_cnt[s];
    int end = start + cnt;

    float4 acc = make_float4(0.f, 0.f, 0.f, 0.f);

    // pass 1: accumulate (2 rows in flight per warp)
    int j = start;
    for (; j + 1 < end; j += 2) {
        int r0 = g_perm[j];
        int r1 = g_perm[j + 1];
        const float* s0 = x + (size_t)r0 * FDIM + lane * 4;
        const float* s1 = x + (size_t)r1 * FDIM + lane * 4;
        float4 v0, v1;
        asm volatile("ld.global.cs.v4.f32 {%0, %1, %2, %3}, [%4];"
                     : "=f"(v0.x), "=f"(v0.y), "=f"(v0.z), "=f"(v0.w) : "l"(s0));
        asm volatile("ld.global.cs.v4.f32 {%0, %1, %2, %3}, [%4];"
                     : "=f"(v1.x), "=f"(v1.y), "=f"(v1.z), "=f"(v1.w) : "l"(s1));
        acc.x += v0.x + v1.x; acc.y += v0.y + v1.y;
        acc.z += v0.z + v1.z; acc.w += v0.w + v1.w;
    }
    if (j < end) {
        int r0 = g_perm[j];
        const float* s0 = x + (size_t)r0 * FDIM + lane * 4;
        float4 v0;
        asm volatile("ld.global.cs.v4.f32 {%0, %1, %2, %3}, [%4];"
                     : "=f"(v0.x), "=f"(v0.y), "=f"(v0.z), "=f"(v0.w) : "l"(s0));
        acc.x += v0.x; acc.y += v0.y; acc.z += v0.z; acc.w += v0.w;
    }

    float inv = 1.0f / ((float)cnt + 1e-9f);
    acc.x *= inv; acc.y *= inv; acc.z *= inv; acc.w *= inv;

    // pass 2: write mean to every row of this segment (perm list is L2-hot)
    for (j = start; j < end; j++) {
        int r = g_perm[j];
        float* o = out + (size_t)r * FDIM + lane * 4;
        asm volatile("st.global.cs.v4.f32 [%0], {%1, %2, %3, %4};"
                     :: "l"(o), "f"(acc.x), "f"(acc.y), "f"(acc.z), "f"(acc.w)
                     : "memory");
    }
}

// ---------------------------------------------------------------------------
extern "C" void kernel_launch(void* const* d_in, const int* in_sizes, int n_in,
                              void* d_out, int out_size) {
    const float* x   = (const float*)d_in[0];
    const int* index = (const int*)d_in[1];
    float* out = (float*)d_out;

    int N = in_sizes[1];

    zero_cnt_kernel<<<98, 256>>>();
    hist_kernel<<<1184, 256>>>(index, N);
    scan1_kernel<<<NCHUNKS, CHUNK>>>();
    scan2_kernel<<<1, 256>>>();
    scan3_kernel<<<NCHUNKS, CHUNK>>>();
    perm_kernel<<<1184, 256>>>(index, N);

    // fused reduce+gather: warp per segment
    {
        int threads = 256;
        int segs_per_block = threads / 32;
        int blocks = (OUT_SEGS + segs_per_block - 1) / segs_per_block;
        reduce_write_kernel<<<blocks, threads>>>(x, out);
    }
}